// round 6
// baseline (speedup 1.0000x reference)
#include <cuda_runtime.h>
#include <math.h>

#define NCTA 8
#define NTHR 512
#define HID  128
#define BINS 513
#define WIN  1024
#define ENCN 256

__device__ __forceinline__ float wsum(float v){
#pragma unroll
    for (int o = 16; o > 0; o >>= 1) v += __shfl_xor_sync(0xffffffffu, v, o);
    return v;
}
__device__ __forceinline__ float sigm(float x){ return 1.0f/(1.0f+__expf(-x)); }

__device__ __forceinline__ unsigned su32(const void* p){
    unsigned a;
    asm("{ .reg .u64 t; cvta.to.shared.u64 t, %1; cvt.u32.u64 %0, t; }" : "=r"(a) : "l"(p));
    return a;
}
// Plain 4B push into rank's smem mirror (readiness handled by mbarrier).
__device__ __forceinline__ void push4(unsigned laddr, float v, unsigned rank){
    unsigned ra;
    asm volatile("mapa.shared::cluster.u32 %0, %1, %2;" : "=r"(ra) : "r"(laddr), "r"(rank));
    asm volatile("st.shared::cluster.b32 [%0], %1;" :: "r"(ra), "r"(__float_as_uint(v)) : "memory");
}
__device__ __forceinline__ void bar_arrive_remote(unsigned laddr, unsigned rank){
    unsigned ra;
    asm volatile("mapa.shared::cluster.u32 %0, %1, %2;" : "=r"(ra) : "r"(laddr), "r"(rank));
    asm volatile("mbarrier.arrive.release.cluster.shared::cluster.b64 _, [%0];"
                 :: "r"(ra) : "memory");
}
// Sleep-wait on local mbarrier, phase parity 0, cluster-scope acquire.
__device__ __forceinline__ void bar_wait(unsigned laddr){
    unsigned done;
    asm volatile(
        "{\n\t.reg .pred p;\n\t"
        "mbarrier.try_wait.parity.acquire.cluster.shared::cta.b64 p, [%1], %2;\n\t"
        "selp.b32 %0, 1, 0, p;\n\t}"
        : "=r"(done) : "r"(laddr), "r"(0u) : "memory");
    if (!done){
        asm volatile(
            "{\n\t.reg .pred P1;\n\t"
            "W_%=:\n\t"
            "mbarrier.try_wait.parity.acquire.cluster.shared::cta.b64 P1, [%0], %1, 0x989680;\n\t"
            "@P1 bra.uni D_%=;\n\t"
            "bra.uni W_%=;\n\t"
            "D_%=:\n\t}"
            :: "r"(laddr), "r"(0u) : "memory");
    }
}
// Producer-side stage commit: make pushes visible, then arrive on all ranks.
__device__ __forceinline__ void stage_commit(unsigned baraddr, int tid){
    asm volatile("fence.acq_rel.cluster;" ::: "memory");
    __syncthreads();
    if (tid == 0){
#pragma unroll
        for (unsigned r = 0; r < NCTA; r++) bar_arrive_remote(baraddr, r);
    }
}

struct __align__(16) Smem {
    float  h1[HID];
    float  h2[HID];
    float  h1b[HID];
    float  h2b[HID];
    float  sr[BINS+3];
    float  si[BINS+3];
    float  y1[WIN];
    float  enc[ENCN];
    float  est[ENCN];
    float2 tw[WIN + 32];
    float  encn[ENCN];
    float  red[16];
    float  red2[16];
    unsigned long long mbar[8];
};

__global__ void __launch_bounds__(NTHR, 1) __cluster_dims__(NCTA, 1, 1)
dtln_kernel(
    const float* __restrict__ mag,   const float* __restrict__ phase,
    const float* __restrict__ st1,   const float* __restrict__ st2,
    const float* __restrict__ wih10, const float* __restrict__ whh10,
    const float* __restrict__ bih10, const float* __restrict__ bhh10,
    const float* __restrict__ wih11, const float* __restrict__ whh11,
    const float* __restrict__ bih11, const float* __restrict__ bhh11,
    const float* __restrict__ d1w,   const float* __restrict__ d1b,
    const float* __restrict__ encw,  const float* __restrict__ gamma_,
    const float* __restrict__ beta_,
    const float* __restrict__ wih20, const float* __restrict__ whh20,
    const float* __restrict__ bih20, const float* __restrict__ bhh20,
    const float* __restrict__ wih21, const float* __restrict__ whh21,
    const float* __restrict__ bih21, const float* __restrict__ bhh21,
    const float* __restrict__ d2w,   const float* __restrict__ d2b,
    const float* __restrict__ decw,
    float* __restrict__ out)
{
    __shared__ Smem sm;
    const int tid  = threadIdx.x;
    const int lane = tid & 31;
    const int wid  = tid >> 5;
    const int cta  = blockIdx.x;
    const int gw   = cta * 16 + wid;      // 0..127

    const unsigned a_h1  = su32(sm.h1);
    const unsigned a_h2  = su32(sm.h2);
    const unsigned a_h1b = su32(sm.h1b);
    const unsigned a_h2b = su32(sm.h2b);
    const unsigned a_sr  = su32(sm.sr);
    const unsigned a_si  = su32(sm.si);
    const unsigned a_y1  = su32(sm.y1);
    const unsigned a_enc = su32(sm.enc);
    const unsigned a_est = su32(sm.est);
    const unsigned a_bar = su32(sm.mbar);
    // stage barriers: 0:h1 1:h2 2:spec 3:y1 4:enc 5:h1b 6:h2b 7:est

    // ---- entry: init barriers, twiddle table, cluster sync ----
    if (tid == 0){
#pragma unroll
        for (int s = 0; s < 8; s++)
            asm volatile("mbarrier.init.shared.b64 [%0], %1;"
                         :: "r"(a_bar + s*8), "r"((unsigned)NCTA) : "memory");
    }
    {
        for (int m = tid; m < WIN; m += NTHR){
            float s, c; sincospif((float)m * (1.0f/512.0f), &s, &c);
            sm.tw[m + (m >> 5)] = make_float2(c, s);
        }
    }
    __syncthreads();
    asm volatile("barrier.cluster.arrive.aligned;" ::: "memory");

    // ---- S1 preloads hidden under cluster wait ----
    float wiA[4][17], whA[4][4], bA[4], hrA[4], xrA[17], cprevA;
    {
#pragma unroll
        for (int g = 0; g < 4; g++){
            const float* w = wih10 + (size_t)(g*HID + gw)*BINS;
#pragma unroll
            for (int i = 0; i < 17; i++){ int k = lane + 32*i; wiA[g][i] = (k < BINS) ? w[k] : 0.f; }
            const float* wh = whh10 + (size_t)(g*HID + gw)*HID;
#pragma unroll
            for (int i = 0; i < 4; i++) whA[g][i] = wh[lane + 32*i];
            bA[g] = bih10[g*HID + gw] + bhh10[g*HID + gw];
        }
#pragma unroll
        for (int i = 0; i < 17; i++){ int k = lane + 32*i; xrA[i] = (k < BINS) ? mag[k] : 0.f; }
#pragma unroll
        for (int i = 0; i < 4; i++) hrA[i] = st1[lane + 32*i];
        cprevA = st1[2*HID + gw];
    }
    asm volatile("barrier.cluster.wait.aligned;" ::: "memory");

    // ================= S1: LSTM1 layer0 =================
    {
        float a[4];
#pragma unroll
        for (int g = 0; g < 4; g++){
            float acc = 0.f;
#pragma unroll
            for (int i = 0; i < 17; i++) acc = fmaf(wiA[g][i], xrA[i], acc);
#pragma unroll
            for (int i = 0; i < 4; i++)  acc = fmaf(whA[g][i], hrA[i], acc);
            a[g] = wsum(acc) + bA[g];
        }
        float c2 = sigm(a[1])*cprevA + sigm(a[0])*tanhf(a[2]);
        float h2 = sigm(a[3])*tanhf(c2);
        if (lane == 0){ out[WIN + gw] = h2; out[WIN + 2*HID + gw] = c2; }
        if (lane < NCTA) push4(a_h1 + gw*4, h2, lane);
    }
    stage_commit(a_bar + 0*8, tid);

    // ================= S2: LSTM1 layer1 =================
    {
        float4 wiB[4], whB[4]; float bB[4];
#pragma unroll
        for (int g = 0; g < 4; g++){
            wiB[g] = *(const float4*)(wih11 + (size_t)(g*HID + gw)*HID + lane*4);
            whB[g] = *(const float4*)(whh11 + (size_t)(g*HID + gw)*HID + lane*4);
            bB[g]  = bih11[g*HID + gw] + bhh11[g*HID + gw];
        }
        float4 hrB = *(const float4*)(st1 + HID + lane*4);
        float cprevB = st1[3*HID + gw];
        bar_wait(a_bar + 0*8);
        float4 xB = *(const float4*)&sm.h1[lane*4];
        float a[4];
#pragma unroll
        for (int g = 0; g < 4; g++){
            float acc = wiB[g].x*xB.x + wiB[g].y*xB.y + wiB[g].z*xB.z + wiB[g].w*xB.w
                      + whB[g].x*hrB.x + whB[g].y*hrB.y + whB[g].z*hrB.z + whB[g].w*hrB.w;
            a[g] = wsum(acc) + bB[g];
        }
        float c2 = sigm(a[1])*cprevB + sigm(a[0])*tanhf(a[2]);
        float h2 = sigm(a[3])*tanhf(c2);
        if (lane == 0){ out[WIN + HID + gw] = h2; out[WIN + 3*HID + gw] = c2; }
        if (lane < NCTA) push4(a_h2 + gw*4, h2, lane);
    }
    stage_commit(a_bar + 1*8, tid);

    // ================= S3: dense1 -> complex spectrum =================
    {
        int r0 = gw*4;
        float4 wD0 = *(const float4*)(d1w + (size_t)(r0+0)*HID + lane*4);
        float4 wD1 = *(const float4*)(d1w + (size_t)(r0+1)*HID + lane*4);
        float4 wD2 = *(const float4*)(d1w + (size_t)(r0+2)*HID + lane*4);
        float4 wD3 = *(const float4*)(d1w + (size_t)(r0+3)*HID + lane*4);
        float b0 = d1b[r0+0], b1 = d1b[r0+1], b2 = d1b[r0+2], b3 = d1b[r0+3];
        float m0 = mag[r0+0], m1 = mag[r0+1], m2 = mag[r0+2], m3 = mag[r0+3];
        float c0,s0,c1,s1,c2,s2,c3,s3;
        sincosf(phase[r0+0], &s0, &c0);  sincosf(phase[r0+1], &s1, &c1);
        sincosf(phase[r0+2], &s2, &c2);  sincosf(phase[r0+3], &s3, &c3);
        float4 w512; float b5=0.f, m5=0.f, c5=1.f, s5=0.f;
        if (gw == 127){
            w512 = *(const float4*)(d1w + (size_t)512*HID + lane*4);
            b5 = d1b[512]; m5 = mag[512];
            sincosf(phase[512], &s5, &c5);
        }
        bar_wait(a_bar + 1*8);
        float4 x = *(const float4*)&sm.h2[lane*4];
        float a0 = wsum(wD0.x*x.x+wD0.y*x.y+wD0.z*x.z+wD0.w*x.w) + b0;
        float a1 = wsum(wD1.x*x.x+wD1.y*x.y+wD1.z*x.z+wD1.w*x.w) + b1;
        float a2 = wsum(wD2.x*x.x+wD2.y*x.y+wD2.z*x.z+wD2.w*x.w) + b2;
        float a3 = wsum(wD3.x*x.x+wD3.y*x.y+wD3.z*x.z+wD3.w*x.w) + b3;
        float e0 = sigm(a0)*m0, e1 = sigm(a1)*m1, e2 = sigm(a2)*m2, e3 = sigm(a3)*m3;
        float re0=e0*c0, im0=e0*s0, re1=e1*c1, im1=e1*s1;
        float re2=e2*c2, im2=e2*s2, re3=e3*c3, im3=e3*s3;
#pragma unroll
        for (int half = 0; half < 2; half++){
            int id   = lane + 32*half;
            int row  = id >> 4;
            int comp = (id >> 3) & 1;
            int rank = id & 7;
            float rv = (row == 0) ? re0 : ((row == 1) ? re1 : ((row == 2) ? re2 : re3));
            float iv = (row == 0) ? im0 : ((row == 1) ? im1 : ((row == 2) ? im2 : im3));
            push4((comp ? a_si : a_sr) + (unsigned)(r0 + row)*4, comp ? iv : rv, (unsigned)rank);
        }
        if (gw == 127){
            float a5 = wsum(w512.x*x.x+w512.y*x.y+w512.z*x.z+w512.w*x.w) + b5;
            float e5 = sigm(a5)*m5;
            if (lane < 16){
                int comp = lane >> 3, rank = lane & 7;
                push4((comp ? a_si : a_sr) + 512u*4u, comp ? e5*s5 : e5*c5, (unsigned)rank);
            }
        }
    }
    stage_commit(a_bar + 2*8, tid);

    // ===== S5 weight prefetch (before iDFT wait) =====
    float4 wE[2][8];
    const int enc0 = gw*2;
    {
#pragma unroll
        for (int rr = 0; rr < 2; rr++)
#pragma unroll
            for (int c = 0; c < 8; c++)
                wE[rr][c] = *(const float4*)(encw + (size_t)(enc0+rr)*WIN + c*128 + lane*4);
    }

    // ================= S4: iDFT (outputs gw*8..+7) =================
    {
        bar_wait(a_bar + 2*8);
        float dc  = sm.sr[0];
        float nyq = sm.sr[512];
        int n0 = gw*8;
        float acc[8] = {0.f,0.f,0.f,0.f,0.f,0.f,0.f,0.f};
#pragma unroll
        for (int t = 0; t < 16; t++){
            int k = 1 + lane + 32*t;
            if (k < 512){
                float sr_ = sm.sr[k], si_ = sm.si[k];
                int base = (k * n0) & (WIN-1);
#pragma unroll
                for (int q = 0; q < 8; q++){
                    int idx = (base + q*k) & (WIN-1);
                    float2 cs = sm.tw[idx + (idx >> 5)];
                    acc[q] = fmaf(sr_, cs.x, acc[q]);
                    acc[q] = fmaf(-si_, cs.y, acc[q]);
                }
            }
        }
        float yv[8];
#pragma unroll
        for (int q = 0; q < 8; q++){
            float a = wsum(acc[q]);
            int n = n0 + q;
            float ny = (n & 1) ? -nyq : nyq;
            yv[q] = (dc + 2.0f*a + ny) * (1.0f/1024.0f);
        }
#pragma unroll
        for (int half = 0; half < 2; half++){
            int id = lane + 32*half;
            int q  = id >> 3;
            int rank = id & 7;
            float v = (q < 4) ? ((q < 2) ? (q ? yv[1] : yv[0]) : (q == 2 ? yv[2] : yv[3]))
                              : ((q < 6) ? (q == 4 ? yv[4] : yv[5]) : (q == 6 ? yv[6] : yv[7]));
            push4(a_y1 + (unsigned)(n0 + q)*4, v, (unsigned)rank);
        }
    }
    stage_commit(a_bar + 3*8, tid);

    // ================= S5: encoder rows enc0, enc0+1 =================
    {
        bar_wait(a_bar + 3*8);
        float ea = 0.f, eb = 0.f;
#pragma unroll
        for (int c = 0; c < 8; c++){
            float4 y = *(const float4*)&sm.y1[c*128 + lane*4];
            ea = fmaf(wE[0][c].x, y.x, ea); ea = fmaf(wE[0][c].y, y.y, ea);
            ea = fmaf(wE[0][c].z, y.z, ea); ea = fmaf(wE[0][c].w, y.w, ea);
            eb = fmaf(wE[1][c].x, y.x, eb); eb = fmaf(wE[1][c].y, y.y, eb);
            eb = fmaf(wE[1][c].z, y.z, eb); eb = fmaf(wE[1][c].w, y.w, eb);
        }
        ea = wsum(ea); eb = wsum(eb);
        if (lane < 16){
            int rr = lane >> 3, rank = lane & 7;
            push4(a_enc + (unsigned)(enc0 + rr)*4, rr ? eb : ea, (unsigned)rank);
        }
    }
    stage_commit(a_bar + 4*8, tid);

    // ================= S6: instance norm + LSTM2 layer0 =================
    {
        float4 wiC0[4], wiC1[4], whC[4]; float bC[4];
#pragma unroll
        for (int g = 0; g < 4; g++){
            wiC0[g] = *(const float4*)(wih20 + (size_t)(g*HID + gw)*ENCN + lane*8);
            wiC1[g] = *(const float4*)(wih20 + (size_t)(g*HID + gw)*ENCN + lane*8 + 4);
            whC[g]  = *(const float4*)(whh20 + (size_t)(g*HID + gw)*HID + lane*4);
            bC[g]   = bih20[g*HID + gw] + bhh20[g*HID + gw];
        }
        float4 hrC = *(const float4*)(st2 + lane*4);
        float cprevC = st2[2*HID + gw];
        float gamv = 0.f, betv = 0.f;
        if (tid < ENCN){ gamv = gamma_[tid]; betv = beta_[tid]; }

        bar_wait(a_bar + 4*8);
        float v = (tid < ENCN) ? sm.enc[tid] : 0.f;
        float t1 = wsum(v);
        if (lane == 0) sm.red[wid] = t1;
        __syncthreads();
        float tot = 0.f;
#pragma unroll
        for (int i = 0; i < 16; i++) tot += sm.red[i];
        float mean = tot * (1.0f/ENCN);
        float d = (tid < ENCN) ? (v - mean) : 0.f;
        float t2 = wsum(d*d);
        if (lane == 0) sm.red2[wid] = t2;
        __syncthreads();
        float tot2 = 0.f;
#pragma unroll
        for (int i = 0; i < 16; i++) tot2 += sm.red2[i];
        float rstd = rsqrtf(tot2 * (1.0f/ENCN) + 1e-7f);
        if (tid < ENCN) sm.encn[tid] = d * rstd * gamv + betv;
        __syncthreads();

        float4 x0 = *(const float4*)&sm.encn[lane*8];
        float4 x1 = *(const float4*)&sm.encn[lane*8 + 4];
        float a[4];
#pragma unroll
        for (int g = 0; g < 4; g++){
            float acc = wiC0[g].x*x0.x + wiC0[g].y*x0.y + wiC0[g].z*x0.z + wiC0[g].w*x0.w
                      + wiC1[g].x*x1.x + wiC1[g].y*x1.y + wiC1[g].z*x1.z + wiC1[g].w*x1.w
                      + whC[g].x*hrC.x + whC[g].y*hrC.y + whC[g].z*hrC.z + whC[g].w*hrC.w;
            a[g] = wsum(acc) + bC[g];
        }
        float c2 = sigm(a[1])*cprevC + sigm(a[0])*tanhf(a[2]);
        float h2 = sigm(a[3])*tanhf(c2);
        if (lane == 0){ out[WIN + 4*HID + gw] = h2; out[WIN + 6*HID + gw] = c2; }
        if (lane < NCTA) push4(a_h1b + gw*4, h2, lane);
    }
    stage_commit(a_bar + 5*8, tid);

    // ================= S7: LSTM2 layer1 =================
    {
        float4 wiB[4], whB[4]; float bB[4];
#pragma unroll
        for (int g = 0; g < 4; g++){
            wiB[g] = *(const float4*)(wih21 + (size_t)(g*HID + gw)*HID + lane*4);
            whB[g] = *(const float4*)(whh21 + (size_t)(g*HID + gw)*HID + lane*4);
            bB[g]  = bih21[g*HID + gw] + bhh21[g*HID + gw];
        }
        float4 hrB = *(const float4*)(st2 + HID + lane*4);
        float cprevB = st2[3*HID + gw];
        bar_wait(a_bar + 5*8);
        float4 xB = *(const float4*)&sm.h1b[lane*4];
        float a[4];
#pragma unroll
        for (int g = 0; g < 4; g++){
            float acc = wiB[g].x*xB.x + wiB[g].y*xB.y + wiB[g].z*xB.z + wiB[g].w*xB.w
                      + whB[g].x*hrB.x + whB[g].y*hrB.y + whB[g].z*hrB.z + whB[g].w*hrB.w;
            a[g] = wsum(acc) + bB[g];
        }
        float c2 = sigm(a[1])*cprevB + sigm(a[0])*tanhf(a[2]);
        float h2 = sigm(a[3])*tanhf(c2);
        if (lane == 0){ out[WIN + 5*HID + gw] = h2; out[WIN + 7*HID + gw] = c2; }
        if (lane < NCTA) push4(a_h2b + gw*4, h2, lane);
    }
    stage_commit(a_bar + 6*8, tid);

    // ================= S8: dense2 -> est =================
    {
        int r2 = gw*2;
        float4 wF0 = *(const float4*)(d2w + (size_t)(r2+0)*HID + lane*4);
        float4 wF1 = *(const float4*)(d2w + (size_t)(r2+1)*HID + lane*4);
        float bF0 = d2b[r2+0], bF1 = d2b[r2+1];
        bar_wait(a_bar + 6*8);
        float ev0 = sm.enc[r2+0], ev1 = sm.enc[r2+1];
        float4 x = *(const float4*)&sm.h2b[lane*4];
        float a0 = wsum(wF0.x*x.x+wF0.y*x.y+wF0.z*x.z+wF0.w*x.w) + bF0;
        float a1 = wsum(wF1.x*x.x+wF1.y*x.y+wF1.z*x.z+wF1.w*x.w) + bF1;
        float es0 = sigm(a0)*ev0, es1 = sigm(a1)*ev1;
        if (lane < 16){
            int rr = lane >> 3, rank = lane & 7;
            push4(a_est + (unsigned)(r2 + rr)*4, rr ? es1 : es0, (unsigned)rank);
        }
    }
    stage_commit(a_bar + 7*8, tid);

    // ================= S9: decoder rows gw*8..+7 =================
    {
        int n0 = gw*8;
        float4 wD[8][2];
#pragma unroll
        for (int q = 0; q < 8; q++){
            wD[q][0] = *(const float4*)(decw + (size_t)(n0+q)*ENCN + lane*8);
            wD[q][1] = *(const float4*)(decw + (size_t)(n0+q)*ENCN + lane*8 + 4);
        }
        bar_wait(a_bar + 7*8);
        float4 e0v = *(const float4*)&sm.est[lane*8];
        float4 e1v = *(const float4*)&sm.est[lane*8 + 4];
#pragma unroll
        for (int q = 0; q < 8; q++){
            float acc = wD[q][0].x*e0v.x + wD[q][0].y*e0v.y + wD[q][0].z*e0v.z + wD[q][0].w*e0v.w
                      + wD[q][1].x*e1v.x + wD[q][1].y*e1v.y + wD[q][1].z*e1v.z + wD[q][1].w*e1v.w;
            acc = wsum(acc);
            if (lane == 0) out[n0 + q] = acc;
        }
    }
}

extern "C" void kernel_launch(void* const* d_in, const int* in_sizes, int n_in,
                              void* d_out, int out_size)
{
    (void)in_sizes; (void)n_in; (void)out_size;
    dtln_kernel<<<NCTA, NTHR>>>(
        (const float*)d_in[0],  (const float*)d_in[1],
        (const float*)d_in[2],  (const float*)d_in[3],
        (const float*)d_in[4],  (const float*)d_in[5],
        (const float*)d_in[6],  (const float*)d_in[7],
        (const float*)d_in[8],  (const float*)d_in[9],
        (const float*)d_in[10], (const float*)d_in[11],
        (const float*)d_in[12], (const float*)d_in[13],
        (const float*)d_in[14], (const float*)d_in[15],
        (const float*)d_in[16],
        (const float*)d_in[17], (const float*)d_in[18],
        (const float*)d_in[19], (const float*)d_in[20],
        (const float*)d_in[21], (const float*)d_in[22],
        (const float*)d_in[23], (const float*)d_in[24],
        (const float*)d_in[25], (const float*)d_in[26],
        (const float*)d_in[27],
        (float*)d_out);
}

// round 7
// speedup vs baseline: 1.2821x; 1.2821x over previous
#include <cuda_runtime.h>
#include <math.h>

#define NCTA 8
#define NTHR 512
#define HID  128
#define BINS 513
#define WIN  1024
#define ENCN 256

__device__ __forceinline__ float wsum(float v){
#pragma unroll
    for (int o = 16; o > 0; o >>= 1) v += __shfl_xor_sync(0xffffffffu, v, o);
    return v;
}
__device__ __forceinline__ float sigm(float x){ return 1.0f/(1.0f+__expf(-x)); }

__device__ __forceinline__ unsigned su32(const void* p){
    unsigned a;
    asm("{ .reg .u64 t; cvta.to.shared.u64 t, %1; cvt.u32.u64 %0, t; }" : "=r"(a) : "l"(p));
    return a;
}
__device__ __forceinline__ unsigned mapa_u32(unsigned laddr, unsigned rank){
    unsigned ra;
    asm volatile("mapa.shared::cluster.u32 %0, %1, %2;" : "=r"(ra) : "r"(laddr), "r"(rank));
    return ra;
}
__device__ __forceinline__ void st_rem(unsigned raddr, float v){
    asm volatile("st.shared::cluster.b32 [%0], %1;" :: "r"(raddr), "r"(__float_as_uint(v)) : "memory");
}
// Release-arrive on the (already mapa'd) remote barrier: orders THIS lane's
// prior remote smem stores against the consumer's acquire-wait.
__device__ __forceinline__ void arrive_rel(unsigned raddr){
    asm volatile("mbarrier.arrive.release.cluster.shared::cluster.b64 _, [%0];"
                 :: "r"(raddr) : "memory");
}
// Sleep-wait on local mbarrier, phase parity 0, cluster-scope acquire.
__device__ __forceinline__ void bar_wait(unsigned laddr){
    unsigned done;
    asm volatile(
        "{\n\t.reg .pred p;\n\t"
        "mbarrier.try_wait.parity.acquire.cluster.shared::cta.b64 p, [%1], %2;\n\t"
        "selp.b32 %0, 1, 0, p;\n\t}"
        : "=r"(done) : "r"(laddr), "r"(0u) : "memory");
    if (!done){
        asm volatile(
            "{\n\t.reg .pred P1;\n\t"
            "W_%=:\n\t"
            "mbarrier.try_wait.parity.acquire.cluster.shared::cta.b64 P1, [%0], %1, 0x3E8;\n\t"
            "@P1 bra.uni D_%=;\n\t"
            "bra.uni W_%=;\n\t"
            "D_%=:\n\t}"
            :: "r"(laddr), "r"(0u) : "memory");
    }
}

struct __align__(16) Smem {
    float  h1[HID];
    float  h2[HID];
    float  h1b[HID];
    float  h2b[HID];
    float  sr[BINS+3];
    float  si[BINS+3];
    float  y1[WIN];
    float  enc[ENCN];
    float  est[ENCN];
    float2 tw[WIN + 32];
    float  encn[ENCN];
    float  red[16];
    float  red2[16];
    unsigned long long mbar[8];
};

__global__ void __launch_bounds__(NTHR, 1) __cluster_dims__(NCTA, 1, 1)
dtln_kernel(
    const float* __restrict__ mag,   const float* __restrict__ phase,
    const float* __restrict__ st1,   const float* __restrict__ st2,
    const float* __restrict__ wih10, const float* __restrict__ whh10,
    const float* __restrict__ bih10, const float* __restrict__ bhh10,
    const float* __restrict__ wih11, const float* __restrict__ whh11,
    const float* __restrict__ bih11, const float* __restrict__ bhh11,
    const float* __restrict__ d1w,   const float* __restrict__ d1b,
    const float* __restrict__ encw,  const float* __restrict__ gamma_,
    const float* __restrict__ beta_,
    const float* __restrict__ wih20, const float* __restrict__ whh20,
    const float* __restrict__ bih20, const float* __restrict__ bhh20,
    const float* __restrict__ wih21, const float* __restrict__ whh21,
    const float* __restrict__ bih21, const float* __restrict__ bhh21,
    const float* __restrict__ d2w,   const float* __restrict__ d2b,
    const float* __restrict__ decw,
    float* __restrict__ out)
{
    __shared__ Smem sm;
    const int tid  = threadIdx.x;
    const int lane = tid & 31;
    const int wid  = tid >> 5;
    const int cta  = blockIdx.x;
    const int gw   = cta * 16 + wid;      // 0..127

    const unsigned a_h1  = su32(sm.h1);
    const unsigned a_h2  = su32(sm.h2);
    const unsigned a_h1b = su32(sm.h1b);
    const unsigned a_h2b = su32(sm.h2b);
    const unsigned a_sr  = su32(sm.sr);
    const unsigned a_si  = su32(sm.si);
    const unsigned a_y1  = su32(sm.y1);
    const unsigned a_enc = su32(sm.enc);
    const unsigned a_est = su32(sm.est);
    const unsigned a_bar = su32(sm.mbar);

    // Per-lane remote bases for this lane's rank (lanes 0-7 are pushers).
    const unsigned rk = (unsigned)(lane & 7);
    const unsigned r_h1  = mapa_u32(a_h1,  rk);
    const unsigned r_h2  = mapa_u32(a_h2,  rk);
    const unsigned r_h1b = mapa_u32(a_h1b, rk);
    const unsigned r_h2b = mapa_u32(a_h2b, rk);
    const unsigned r_sr  = mapa_u32(a_sr,  rk);
    const unsigned r_si  = mapa_u32(a_si,  rk);
    const unsigned r_y1  = mapa_u32(a_y1,  rk);
    const unsigned r_enc = mapa_u32(a_enc, rk);
    const unsigned r_est = mapa_u32(a_est, rk);
    const unsigned r_bar = mapa_u32(a_bar, rk);
    // stage barriers: 0:h1 1:h2 2:spec 3:y1 4:enc 5:h1b 6:h2b 7:est

    // ---- entry: init barriers (expect 128 = one arrive per producer warp) ----
    if (tid == 0){
#pragma unroll
        for (int s = 0; s < 8; s++)
            asm volatile("mbarrier.init.shared.b64 [%0], %1;"
                         :: "r"(a_bar + s*8), "r"(128u) : "memory");
    }
    for (int m = tid; m < WIN; m += NTHR){
        float s, c; sincospif((float)m * (1.0f/512.0f), &s, &c);
        sm.tw[m + (m >> 5)] = make_float2(c, s);
    }
    __syncthreads();
    asm volatile("barrier.cluster.arrive.aligned;" ::: "memory");

    // ---- S1 preloads hidden under cluster wait ----
    float wiA[4][17], whA[4][4], bA[4], hrA[4], xrA[17], cprevA;
    {
#pragma unroll
        for (int g = 0; g < 4; g++){
            const float* w = wih10 + (size_t)(g*HID + gw)*BINS;
#pragma unroll
            for (int i = 0; i < 17; i++){ int k = lane + 32*i; wiA[g][i] = (k < BINS) ? w[k] : 0.f; }
            const float* wh = whh10 + (size_t)(g*HID + gw)*HID;
#pragma unroll
            for (int i = 0; i < 4; i++) whA[g][i] = wh[lane + 32*i];
            bA[g] = bih10[g*HID + gw] + bhh10[g*HID + gw];
        }
#pragma unroll
        for (int i = 0; i < 17; i++){ int k = lane + 32*i; xrA[i] = (k < BINS) ? mag[k] : 0.f; }
#pragma unroll
        for (int i = 0; i < 4; i++) hrA[i] = st1[lane + 32*i];
        cprevA = st1[2*HID + gw];
    }
    asm volatile("barrier.cluster.wait.aligned;" ::: "memory");

    // ================= S1: LSTM1 layer0 =================
    {
        float a[4];
#pragma unroll
        for (int g = 0; g < 4; g++){
            float acc = 0.f;
#pragma unroll
            for (int i = 0; i < 17; i++) acc = fmaf(wiA[g][i], xrA[i], acc);
#pragma unroll
            for (int i = 0; i < 4; i++)  acc = fmaf(whA[g][i], hrA[i], acc);
            a[g] = wsum(acc) + bA[g];
        }
        float c2 = sigm(a[1])*cprevA + sigm(a[0])*tanhf(a[2]);
        float h2 = sigm(a[3])*tanhf(c2);
        if (lane == 0){ out[WIN + gw] = h2; out[WIN + 2*HID + gw] = c2; }
        if (lane < NCTA){ st_rem(r_h1 + gw*4, h2); arrive_rel(r_bar + 0*8); }
    }

    // ================= S2: LSTM1 layer1 =================
    {
        float4 wiB[4], whB[4]; float bB[4];
#pragma unroll
        for (int g = 0; g < 4; g++){
            wiB[g] = *(const float4*)(wih11 + (size_t)(g*HID + gw)*HID + lane*4);
            whB[g] = *(const float4*)(whh11 + (size_t)(g*HID + gw)*HID + lane*4);
            bB[g]  = bih11[g*HID + gw] + bhh11[g*HID + gw];
        }
        float4 hrB = *(const float4*)(st1 + HID + lane*4);
        float cprevB = st1[3*HID + gw];
        bar_wait(a_bar + 0*8);
        float4 xB = *(const float4*)&sm.h1[lane*4];
        float a[4];
#pragma unroll
        for (int g = 0; g < 4; g++){
            float acc = wiB[g].x*xB.x + wiB[g].y*xB.y + wiB[g].z*xB.z + wiB[g].w*xB.w
                      + whB[g].x*hrB.x + whB[g].y*hrB.y + whB[g].z*hrB.z + whB[g].w*hrB.w;
            a[g] = wsum(acc) + bB[g];
        }
        float c2 = sigm(a[1])*cprevB + sigm(a[0])*tanhf(a[2]);
        float h2 = sigm(a[3])*tanhf(c2);
        if (lane == 0){ out[WIN + HID + gw] = h2; out[WIN + 3*HID + gw] = c2; }
        if (lane < NCTA){ st_rem(r_h2 + gw*4, h2); arrive_rel(r_bar + 1*8); }
    }

    // ================= S3: dense1 -> complex spectrum =================
    {
        int r0 = gw*4;
        float4 wD0 = *(const float4*)(d1w + (size_t)(r0+0)*HID + lane*4);
        float4 wD1 = *(const float4*)(d1w + (size_t)(r0+1)*HID + lane*4);
        float4 wD2 = *(const float4*)(d1w + (size_t)(r0+2)*HID + lane*4);
        float4 wD3 = *(const float4*)(d1w + (size_t)(r0+3)*HID + lane*4);
        float b0 = d1b[r0+0], b1 = d1b[r0+1], b2 = d1b[r0+2], b3 = d1b[r0+3];
        float m0 = mag[r0+0], m1 = mag[r0+1], m2 = mag[r0+2], m3 = mag[r0+3];
        float c0,s0,c1,s1,c2,s2,c3,s3;
        sincosf(phase[r0+0], &s0, &c0);  sincosf(phase[r0+1], &s1, &c1);
        sincosf(phase[r0+2], &s2, &c2);  sincosf(phase[r0+3], &s3, &c3);
        float4 w512; float b5=0.f, m5=0.f, c5=1.f, s5=0.f;
        if (gw == 127){
            w512 = *(const float4*)(d1w + (size_t)512*HID + lane*4);
            b5 = d1b[512]; m5 = mag[512];
            sincosf(phase[512], &s5, &c5);
        }
        bar_wait(a_bar + 1*8);
        float4 x = *(const float4*)&sm.h2[lane*4];
        float a0 = wsum(wD0.x*x.x+wD0.y*x.y+wD0.z*x.z+wD0.w*x.w) + b0;
        float a1 = wsum(wD1.x*x.x+wD1.y*x.y+wD1.z*x.z+wD1.w*x.w) + b1;
        float a2 = wsum(wD2.x*x.x+wD2.y*x.y+wD2.z*x.z+wD2.w*x.w) + b2;
        float a3 = wsum(wD3.x*x.x+wD3.y*x.y+wD3.z*x.z+wD3.w*x.w) + b3;
        float e0 = sigm(a0)*m0, e1 = sigm(a1)*m1, e2 = sigm(a2)*m2, e3 = sigm(a3)*m3;
        if (lane < NCTA){
            unsigned o = (unsigned)r0*4u;
            st_rem(r_sr + o,      e0*c0);  st_rem(r_si + o,      e0*s0);
            st_rem(r_sr + o + 4,  e1*c1);  st_rem(r_si + o + 4,  e1*s1);
            st_rem(r_sr + o + 8,  e2*c2);  st_rem(r_si + o + 8,  e2*s2);
            st_rem(r_sr + o + 12, e3*c3);  st_rem(r_si + o + 12, e3*s3);
            if (gw == 127){
                float a5 = wD0.x*0.f; // keep compiler calm
                a5 = wsum(w512.x*x.x+w512.y*x.y+w512.z*x.z+w512.w*x.w) + b5;
                float e5 = sigm(a5)*m5;
                st_rem(r_sr + 512u*4u, e5*c5);
                st_rem(r_si + 512u*4u, e5*s5);
            }
            arrive_rel(r_bar + 2*8);
        } else if (gw == 127){
            // non-pusher lanes still participate in the wsum above; nothing else
            float a5 = wsum(w512.x*x.x+w512.y*x.y+w512.z*x.z+w512.w*x.w) + b5;
            (void)a5;
        }
    }

    // ===== S5 weight prefetch (before iDFT wait) =====
    float4 wE[2][8];
    const int enc0 = gw*2;
    {
#pragma unroll
        for (int rr = 0; rr < 2; rr++)
#pragma unroll
            for (int c = 0; c < 8; c++)
                wE[rr][c] = *(const float4*)(encw + (size_t)(enc0+rr)*WIN + c*128 + lane*4);
    }

    // ================= S4: iDFT (outputs gw*8..+7) =================
    {
        bar_wait(a_bar + 2*8);
        float dc  = sm.sr[0];
        float nyq = sm.sr[512];
        int n0 = gw*8;
        float acc[8] = {0.f,0.f,0.f,0.f,0.f,0.f,0.f,0.f};
#pragma unroll
        for (int t = 0; t < 16; t++){
            int k = 1 + lane + 32*t;
            if (k < 512){
                float sr_ = sm.sr[k], si_ = sm.si[k];
                int base = (k * n0) & (WIN-1);
#pragma unroll
                for (int q = 0; q < 8; q++){
                    int idx = (base + q*k) & (WIN-1);
                    float2 cs = sm.tw[idx + (idx >> 5)];
                    acc[q] = fmaf(sr_, cs.x, acc[q]);
                    acc[q] = fmaf(-si_, cs.y, acc[q]);
                }
            }
        }
        float yv[8];
#pragma unroll
        for (int q = 0; q < 8; q++){
            float a = wsum(acc[q]);
            int n = n0 + q;
            float ny = (n & 1) ? -nyq : nyq;
            yv[q] = (dc + 2.0f*a + ny) * (1.0f/1024.0f);
        }
        if (lane < NCTA){
            unsigned o = (unsigned)n0*4u;
#pragma unroll
            for (int q = 0; q < 8; q++) st_rem(r_y1 + o + q*4, yv[q]);
            arrive_rel(r_bar + 3*8);
        }
    }

    // ================= S5: encoder rows enc0, enc0+1 =================
    {
        bar_wait(a_bar + 3*8);
        float ea = 0.f, eb = 0.f;
#pragma unroll
        for (int c = 0; c < 8; c++){
            float4 y = *(const float4*)&sm.y1[c*128 + lane*4];
            ea = fmaf(wE[0][c].x, y.x, ea); ea = fmaf(wE[0][c].y, y.y, ea);
            ea = fmaf(wE[0][c].z, y.z, ea); ea = fmaf(wE[0][c].w, y.w, ea);
            eb = fmaf(wE[1][c].x, y.x, eb); eb = fmaf(wE[1][c].y, y.y, eb);
            eb = fmaf(wE[1][c].z, y.z, eb); eb = fmaf(wE[1][c].w, y.w, eb);
        }
        ea = wsum(ea); eb = wsum(eb);
        if (lane < NCTA){
            st_rem(r_enc + (unsigned)enc0*4u,      ea);
            st_rem(r_enc + (unsigned)(enc0+1)*4u,  eb);
            arrive_rel(r_bar + 4*8);
        }
    }

    // ================= S6: instance norm + LSTM2 layer0 =================
    {
        float4 wiC0[4], wiC1[4], whC[4]; float bC[4];
#pragma unroll
        for (int g = 0; g < 4; g++){
            wiC0[g] = *(const float4*)(wih20 + (size_t)(g*HID + gw)*ENCN + lane*8);
            wiC1[g] = *(const float4*)(wih20 + (size_t)(g*HID + gw)*ENCN + lane*8 + 4);
            whC[g]  = *(const float4*)(whh20 + (size_t)(g*HID + gw)*HID + lane*4);
            bC[g]   = bih20[g*HID + gw] + bhh20[g*HID + gw];
        }
        float4 hrC = *(const float4*)(st2 + lane*4);
        float cprevC = st2[2*HID + gw];
        float gamv = 0.f, betv = 0.f;
        if (tid < ENCN){ gamv = gamma_[tid]; betv = beta_[tid]; }

        bar_wait(a_bar + 4*8);
        float v = (tid < ENCN) ? sm.enc[tid] : 0.f;
        float t1 = wsum(v);
        if (lane == 0) sm.red[wid] = t1;
        __syncthreads();
        float tot = 0.f;
#pragma unroll
        for (int i = 0; i < 16; i++) tot += sm.red[i];
        float mean = tot * (1.0f/ENCN);
        float d = (tid < ENCN) ? (v - mean) : 0.f;
        float t2 = wsum(d*d);
        if (lane == 0) sm.red2[wid] = t2;
        __syncthreads();
        float tot2 = 0.f;
#pragma unroll
        for (int i = 0; i < 16; i++) tot2 += sm.red2[i];
        float rstd = rsqrtf(tot2 * (1.0f/ENCN) + 1e-7f);
        if (tid < ENCN) sm.encn[tid] = d * rstd * gamv + betv;
        __syncthreads();

        float4 x0 = *(const float4*)&sm.encn[lane*8];
        float4 x1 = *(const float4*)&sm.encn[lane*8 + 4];
        float a[4];
#pragma unroll
        for (int g = 0; g < 4; g++){
            float acc = wiC0[g].x*x0.x + wiC0[g].y*x0.y + wiC0[g].z*x0.z + wiC0[g].w*x0.w
                      + wiC1[g].x*x1.x + wiC1[g].y*x1.y + wiC1[g].z*x1.z + wiC1[g].w*x1.w
                      + whC[g].x*hrC.x + whC[g].y*hrC.y + whC[g].z*hrC.z + whC[g].w*hrC.w;
            a[g] = wsum(acc) + bC[g];
        }
        float c2 = sigm(a[1])*cprevC + sigm(a[0])*tanhf(a[2]);
        float h2 = sigm(a[3])*tanhf(c2);
        if (lane == 0){ out[WIN + 4*HID + gw] = h2; out[WIN + 6*HID + gw] = c2; }
        if (lane < NCTA){ st_rem(r_h1b + gw*4, h2); arrive_rel(r_bar + 5*8); }
    }

    // ================= S7: LSTM2 layer1 =================
    {
        float4 wiB[4], whB[4]; float bB[4];
#pragma unroll
        for (int g = 0; g < 4; g++){
            wiB[g] = *(const float4*)(wih21 + (size_t)(g*HID + gw)*HID + lane*4);
            whB[g] = *(const float4*)(whh21 + (size_t)(g*HID + gw)*HID + lane*4);
            bB[g]  = bih21[g*HID + gw] + bhh21[g*HID + gw];
        }
        float4 hrB = *(const float4*)(st2 + HID + lane*4);
        float cprevB = st2[3*HID + gw];
        bar_wait(a_bar + 5*8);
        float4 xB = *(const float4*)&sm.h1b[lane*4];
        float a[4];
#pragma unroll
        for (int g = 0; g < 4; g++){
            float acc = wiB[g].x*xB.x + wiB[g].y*xB.y + wiB[g].z*xB.z + wiB[g].w*xB.w
                      + whB[g].x*hrB.x + whB[g].y*hrB.y + whB[g].z*hrB.z + whB[g].w*hrB.w;
            a[g] = wsum(acc) + bB[g];
        }
        float c2 = sigm(a[1])*cprevB + sigm(a[0])*tanhf(a[2]);
        float h2 = sigm(a[3])*tanhf(c2);
        if (lane == 0){ out[WIN + 5*HID + gw] = h2; out[WIN + 7*HID + gw] = c2; }
        if (lane < NCTA){ st_rem(r_h2b + gw*4, h2); arrive_rel(r_bar + 6*8); }
    }

    // ================= S8: dense2 -> est =================
    {
        int r2 = gw*2;
        float4 wF0 = *(const float4*)(d2w + (size_t)(r2+0)*HID + lane*4);
        float4 wF1 = *(const float4*)(d2w + (size_t)(r2+1)*HID + lane*4);
        float bF0 = d2b[r2+0], bF1 = d2b[r2+1];
        bar_wait(a_bar + 6*8);
        float ev0 = sm.enc[r2+0], ev1 = sm.enc[r2+1];
        float4 x = *(const float4*)&sm.h2b[lane*4];
        float a0 = wsum(wF0.x*x.x+wF0.y*x.y+wF0.z*x.z+wF0.w*x.w) + bF0;
        float a1 = wsum(wF1.x*x.x+wF1.y*x.y+wF1.z*x.z+wF1.w*x.w) + bF1;
        float es0 = sigm(a0)*ev0, es1 = sigm(a1)*ev1;
        if (lane < NCTA){
            st_rem(r_est + (unsigned)r2*4u,     es0);
            st_rem(r_est + (unsigned)(r2+1)*4u, es1);
            arrive_rel(r_bar + 7*8);
        }
    }

    // ================= S9: decoder rows gw*8..+7 =================
    {
        int n0 = gw*8;
        float4 wD[8][2];
#pragma unroll
        for (int q = 0; q < 8; q++){
            wD[q][0] = *(const float4*)(decw + (size_t)(n0+q)*ENCN + lane*8);
            wD[q][1] = *(const float4*)(decw + (size_t)(n0+q)*ENCN + lane*8 + 4);
        }
        bar_wait(a_bar + 7*8);
        float4 e0v = *(const float4*)&sm.est[lane*8];
        float4 e1v = *(const float4*)&sm.est[lane*8 + 4];
#pragma unroll
        for (int q = 0; q < 8; q++){
            float acc = wD[q][0].x*e0v.x + wD[q][0].y*e0v.y + wD[q][0].z*e0v.z + wD[q][0].w*e0v.w
                      + wD[q][1].x*e1v.x + wD[q][1].y*e1v.y + wD[q][1].z*e1v.z + wD[q][1].w*e1v.w;
            acc = wsum(acc);
            if (lane == 0) out[n0 + q] = acc;
        }
    }
}

extern "C" void kernel_launch(void* const* d_in, const int* in_sizes, int n_in,
                              void* d_out, int out_size)
{
    (void)in_sizes; (void)n_in; (void)out_size;
    dtln_kernel<<<NCTA, NTHR>>>(
        (const float*)d_in[0],  (const float*)d_in[1],
        (const float*)d_in[2],  (const float*)d_in[3],
        (const float*)d_in[4],  (const float*)d_in[5],
        (const float*)d_in[6],  (const float*)d_in[7],
        (const float*)d_in[8],  (const float*)d_in[9],
        (const float*)d_in[10], (const float*)d_in[11],
        (const float*)d_in[12], (const float*)d_in[13],
        (const float*)d_in[14], (const float*)d_in[15],
        (const float*)d_in[16],
        (const float*)d_in[17], (const float*)d_in[18],
        (const float*)d_in[19], (const float*)d_in[20],
        (const float*)d_in[21], (const float*)d_in[22],
        (const float*)d_in[23], (const float*)d_in[24],
        (const float*)d_in[25], (const float*)d_in[26],
        (const float*)d_in[27],
        (float*)d_out);
}

// round 9
// speedup vs baseline: 1.4545x; 1.1345x over previous
#include <cuda_runtime.h>
#include <math.h>

#define NBLK 128
#define NTHR 256
#define HID  128
#define BINS 513
#define WIN  1024
#define ENCN 256

// ---------------- device scratch ----------------
__device__ __align__(16) float g_h1[HID], g_h2[HID], g_h1b[HID], g_h2b[HID];
__device__ __align__(16) float g_sr[BINS+3], g_si[BINS+3];
__device__ __align__(16) float g_y1[WIN];
__device__ __align__(16) float g_enc[ENCN], g_est[ENCN];
__device__ unsigned g_cnt[9*32];          // one counter per 128B; self-reset

#define CNT(i) (&g_cnt[(i)*32])

__device__ __forceinline__ float sigm(float x){ return 1.0f/(1.0f+__expf(-x)); }

__device__ __forceinline__ float wsum(float v){
#pragma unroll
    for (int o = 16; o > 0; o >>= 1) v += __shfl_xor_sync(0xffffffffu, v, o);
    return v;
}
__device__ __forceinline__ void wsum2(float& a, float& b){
#pragma unroll
    for (int o = 16; o > 0; o >>= 1){
        a += __shfl_xor_sync(0xffffffffu, a, o);
        b += __shfl_xor_sync(0xffffffffu, b, o);
    }
}
__device__ __forceinline__ void wsum4(float& a, float& b, float& c, float& d){
#pragma unroll
    for (int o = 16; o > 0; o >>= 1){
        a += __shfl_xor_sync(0xffffffffu, a, o);
        b += __shfl_xor_sync(0xffffffffu, b, o);
        c += __shfl_xor_sync(0xffffffffu, c, o);
        d += __shfl_xor_sync(0xffffffffu, d, o);
    }
}

__device__ __forceinline__ void redrel(unsigned* p){
    asm volatile("red.release.gpu.global.add.u32 [%0], 1;" :: "l"(p) : "memory");
}
__device__ __forceinline__ unsigned ldacq(const unsigned* p){
    unsigned v;
    asm volatile("ld.acquire.gpu.global.u32 %0, [%1];" : "=r"(v) : "l"(p) : "memory");
    return v;
}
// Producer: all warps' stores -> syncthreads -> cumulative release + count.
__device__ __forceinline__ void signalf(unsigned* c, int tid){
    __syncthreads();
    if (tid == 0){
        asm volatile("fence.acq_rel.gpu;" ::: "memory");
        redrel(c);
    }
}
// Consumer: ONE relay polls (acquire), everyone else parks at syncthreads.
__device__ __forceinline__ void waitf(unsigned* c, unsigned tgt, int tid){
    if (tid == 0){ while (ldacq(c) < tgt) {} }
    __syncthreads();
}

__global__ void __launch_bounds__(NTHR, 1) dtln_kernel(
    const float* __restrict__ mag,   const float* __restrict__ phase,
    const float* __restrict__ st1,   const float* __restrict__ st2,
    const float* __restrict__ wih10, const float* __restrict__ whh10,
    const float* __restrict__ bih10, const float* __restrict__ bhh10,
    const float* __restrict__ wih11, const float* __restrict__ whh11,
    const float* __restrict__ bih11, const float* __restrict__ bhh11,
    const float* __restrict__ d1w,   const float* __restrict__ d1b,
    const float* __restrict__ encw,  const float* __restrict__ gamma_,
    const float* __restrict__ beta_,
    const float* __restrict__ wih20, const float* __restrict__ whh20,
    const float* __restrict__ bih20, const float* __restrict__ bhh20,
    const float* __restrict__ wih21, const float* __restrict__ whh21,
    const float* __restrict__ bih21, const float* __restrict__ bhh21,
    const float* __restrict__ d2w,   const float* __restrict__ d2b,
    const float* __restrict__ decw,
    float* __restrict__ out)
{
    const int tid  = threadIdx.x;
    const int lane = tid & 31;
    const int wid  = tid >> 5;
    const int cta  = blockIdx.x;
    const int gw   = cta * 8 + wid;        // 0..1023

    __shared__ float2 s_tw[WIN + 32];
    __shared__ float  s_encn[ENCN];
    __shared__ float  s_red[8];

    // ---- decoder row preload (every warp, row gw) — BLOCKED layout to match est read ----
    float4 dec0, dec1;
    {
        const float* wr = decw + (size_t)gw*ENCN;
        dec0 = *(const float4*)(wr + lane*8);
        dec1 = *(const float4*)(wr + lane*8 + 4);
    }

    if (cta < 16){
        // ================= A: LSTM1 layer0 (S1) =================
        int j = gw;
        float wiA[4][17], whA[4][4], bA[4], xrA[17], hrA[4];
#pragma unroll
        for (int g = 0; g < 4; g++){
            const float* w = wih10 + (size_t)(g*HID + j)*BINS;
#pragma unroll
            for (int i = 0; i < 17; i++){ int k = lane + 32*i; wiA[g][i] = (k < BINS) ? w[k] : 0.f; }
            const float* wh = whh10 + (size_t)(g*HID + j)*HID;
#pragma unroll
            for (int i = 0; i < 4; i++) whA[g][i] = wh[lane + 32*i];
            bA[g] = bih10[g*HID + j] + bhh10[g*HID + j];
        }
#pragma unroll
        for (int i = 0; i < 17; i++){ int k = lane + 32*i; xrA[i] = (k < BINS) ? mag[k] : 0.f; }
#pragma unroll
        for (int i = 0; i < 4; i++) hrA[i] = st1[lane + 32*i];
        float cprev = st1[2*HID + j];

        float a0=0.f,a1=0.f,a2=0.f,a3=0.f;
#pragma unroll
        for (int i = 0; i < 17; i++){
            float x = xrA[i];
            a0 = fmaf(wiA[0][i], x, a0); a1 = fmaf(wiA[1][i], x, a1);
            a2 = fmaf(wiA[2][i], x, a2); a3 = fmaf(wiA[3][i], x, a3);
        }
#pragma unroll
        for (int i = 0; i < 4; i++){
            float h = hrA[i];
            a0 = fmaf(whA[0][i], h, a0); a1 = fmaf(whA[1][i], h, a1);
            a2 = fmaf(whA[2][i], h, a2); a3 = fmaf(whA[3][i], h, a3);
        }
        wsum4(a0,a1,a2,a3);
        if (lane == 0){
            float c2 = sigm(a1+bA[1])*cprev + sigm(a0+bA[0])*tanhf(a2+bA[2]);
            float h2 = sigm(a3+bA[3])*tanhf(c2);
            out[WIN + j] = h2; out[WIN + 2*HID + j] = c2;
            g_h1[j] = h2;
        }
        signalf(CNT(0), tid);
    }
    else if (cta < 32){
        // ================= B: LSTM1 layer1 (S2) =================
        int j = gw - 128;
        float4 wi[4], wh[4]; float b[4];
#pragma unroll
        for (int g = 0; g < 4; g++){
            wi[g] = *(const float4*)(wih11 + (size_t)(g*HID + j)*HID + lane*4);
            wh[g] = *(const float4*)(whh11 + (size_t)(g*HID + j)*HID + lane*4);
            b[g]  = bih11[g*HID + j] + bhh11[g*HID + j];
        }
        float4 hr = *(const float4*)(st1 + HID + lane*4);
        float cprev = st1[3*HID + j];
        waitf(CNT(0), 16, tid);
        float4 x = __ldcg((const float4*)&g_h1[lane*4]);
        float a0 = wi[0].x*x.x+wi[0].y*x.y+wi[0].z*x.z+wi[0].w*x.w + wh[0].x*hr.x+wh[0].y*hr.y+wh[0].z*hr.z+wh[0].w*hr.w;
        float a1 = wi[1].x*x.x+wi[1].y*x.y+wi[1].z*x.z+wi[1].w*x.w + wh[1].x*hr.x+wh[1].y*hr.y+wh[1].z*hr.z+wh[1].w*hr.w;
        float a2 = wi[2].x*x.x+wi[2].y*x.y+wi[2].z*x.z+wi[2].w*x.w + wh[2].x*hr.x+wh[2].y*hr.y+wh[2].z*hr.z+wh[2].w*hr.w;
        float a3 = wi[3].x*x.x+wi[3].y*x.y+wi[3].z*x.z+wi[3].w*x.w + wh[3].x*hr.x+wh[3].y*hr.y+wh[3].z*hr.z+wh[3].w*hr.w;
        wsum4(a0,a1,a2,a3);
        if (lane == 0){
            float c2 = sigm(a1+b[1])*cprev + sigm(a0+b[0])*tanhf(a2+b[2]);
            float h2 = sigm(a3+b[3])*tanhf(c2);
            out[WIN + HID + j] = h2; out[WIN + 3*HID + j] = c2;
            g_h2[j] = h2;
        }
        signalf(CNT(1), tid);
    }
    else if (cta < 48){
        // ================= C: instance-norm + LSTM2 layer0 (S6) =================
        int j = (cta-32)*8 + wid;
        float4 wi0[4], wi1[4], wh[4]; float b[4];
#pragma unroll
        for (int g = 0; g < 4; g++){
            wi0[g] = *(const float4*)(wih20 + (size_t)(g*HID + j)*ENCN + lane*8);
            wi1[g] = *(const float4*)(wih20 + (size_t)(g*HID + j)*ENCN + lane*8 + 4);
            wh[g]  = *(const float4*)(whh20 + (size_t)(g*HID + j)*HID + lane*4);
            b[g]   = bih20[g*HID + j] + bhh20[g*HID + j];
        }
        float4 hr = *(const float4*)(st2 + lane*4);
        float cprev = st2[2*HID + j];
        float gamv = gamma_[tid], betv = beta_[tid];

        waitf(CNT(4), 32, tid);
        float v = __ldcg(&g_enc[tid]);
        float t1 = wsum(v);
        if (lane == 0) s_red[wid] = t1;
        __syncthreads();
        float tot = 0.f;
#pragma unroll
        for (int i = 0; i < 8; i++) tot += s_red[i];
        float mean = tot * (1.0f/ENCN);
        float d = v - mean;
        float t2 = wsum(d*d);
        __syncthreads();
        if (lane == 0) s_red[wid] = t2;
        __syncthreads();
        float tot2 = 0.f;
#pragma unroll
        for (int i = 0; i < 8; i++) tot2 += s_red[i];
        float rstd = rsqrtf(tot2 * (1.0f/ENCN) + 1e-7f);
        s_encn[tid] = d * rstd * gamv + betv;
        __syncthreads();

        float4 x0 = *(const float4*)&s_encn[lane*8];
        float4 x1 = *(const float4*)&s_encn[lane*8 + 4];
        float a0 = wi0[0].x*x0.x+wi0[0].y*x0.y+wi0[0].z*x0.z+wi0[0].w*x0.w + wi1[0].x*x1.x+wi1[0].y*x1.y+wi1[0].z*x1.z+wi1[0].w*x1.w
                 + wh[0].x*hr.x+wh[0].y*hr.y+wh[0].z*hr.z+wh[0].w*hr.w;
        float a1 = wi0[1].x*x0.x+wi0[1].y*x0.y+wi0[1].z*x0.z+wi0[1].w*x0.w + wi1[1].x*x1.x+wi1[1].y*x1.y+wi1[1].z*x1.z+wi1[1].w*x1.w
                 + wh[1].x*hr.x+wh[1].y*hr.y+wh[1].z*hr.z+wh[1].w*hr.w;
        float a2 = wi0[2].x*x0.x+wi0[2].y*x0.y+wi0[2].z*x0.z+wi0[2].w*x0.w + wi1[2].x*x1.x+wi1[2].y*x1.y+wi1[2].z*x1.z+wi1[2].w*x1.w
                 + wh[2].x*hr.x+wh[2].y*hr.y+wh[2].z*hr.z+wh[2].w*hr.w;
        float a3 = wi0[3].x*x0.x+wi0[3].y*x0.y+wi0[3].z*x0.z+wi0[3].w*x0.w + wi1[3].x*x1.x+wi1[3].y*x1.y+wi1[3].z*x1.z+wi1[3].w*x1.w
                 + wh[3].x*hr.x+wh[3].y*hr.y+wh[3].z*hr.z+wh[3].w*hr.w;
        wsum4(a0,a1,a2,a3);
        if (lane == 0){
            float c2 = sigm(a1+b[1])*cprev + sigm(a0+b[0])*tanhf(a2+b[2]);
            float h2 = sigm(a3+b[3])*tanhf(c2);
            out[WIN + 4*HID + j] = h2; out[WIN + 6*HID + j] = c2;
            g_h1b[j] = h2;
        }
        signalf(CNT(5), tid);
    }
    else if (cta < 64){
        // ================= D: LSTM2 layer1 (S7) =================
        int j = (cta-48)*8 + wid;
        float4 wi[4], wh[4]; float b[4];
#pragma unroll
        for (int g = 0; g < 4; g++){
            wi[g] = *(const float4*)(wih21 + (size_t)(g*HID + j)*HID + lane*4);
            wh[g] = *(const float4*)(whh21 + (size_t)(g*HID + j)*HID + lane*4);
            b[g]  = bih21[g*HID + j] + bhh21[g*HID + j];
        }
        float4 hr = *(const float4*)(st2 + HID + lane*4);
        float cprev = st2[3*HID + j];
        waitf(CNT(5), 16, tid);
        float4 x = __ldcg((const float4*)&g_h1b[lane*4]);
        float a0 = wi[0].x*x.x+wi[0].y*x.y+wi[0].z*x.z+wi[0].w*x.w + wh[0].x*hr.x+wh[0].y*hr.y+wh[0].z*hr.z+wh[0].w*hr.w;
        float a1 = wi[1].x*x.x+wi[1].y*x.y+wi[1].z*x.z+wi[1].w*x.w + wh[1].x*hr.x+wh[1].y*hr.y+wh[1].z*hr.z+wh[1].w*hr.w;
        float a2 = wi[2].x*x.x+wi[2].y*x.y+wi[2].z*x.z+wi[2].w*x.w + wh[2].x*hr.x+wh[2].y*hr.y+wh[2].z*hr.z+wh[2].w*hr.w;
        float a3 = wi[3].x*x.x+wi[3].y*x.y+wi[3].z*x.z+wi[3].w*x.w + wh[3].x*hr.x+wh[3].y*hr.y+wh[3].z*hr.z+wh[3].w*hr.w;
        wsum4(a0,a1,a2,a3);
        if (lane == 0){
            float c2 = sigm(a1+b[1])*cprev + sigm(a0+b[0])*tanhf(a2+b[2]);
            float h2 = sigm(a3+b[3])*tanhf(c2);
            out[WIN + 5*HID + j] = h2; out[WIN + 7*HID + j] = c2;
            g_h2b[j] = h2;
        }
        signalf(CNT(6), tid);
    }
    else if (cta < 96){
        // ================= E: dense1->spectrum (S3), dense2->est (S8) =================
        int ew = (cta-64)*8 + wid;         // 0..255
        int r0 = 2*ew;
        float4 wD0 = *(const float4*)(d1w + (size_t)(r0+0)*HID + lane*4);
        float4 wD1 = *(const float4*)(d1w + (size_t)(r0+1)*HID + lane*4);
        float b0 = d1b[r0+0], b1 = d1b[r0+1];
        float m0 = mag[r0+0], m1 = mag[r0+1];
        float c0,s0,c1,s1;
        sincosf(phase[r0+0], &s0, &c0);  sincosf(phase[r0+1], &s1, &c1);
        float4 w512 = make_float4(0.f,0.f,0.f,0.f);
        float b5=0.f, m5=0.f, c5=1.f, s5=0.f;
        if (ew == 0){
            w512 = *(const float4*)(d1w + (size_t)512*HID + lane*4);
            b5 = d1b[512]; m5 = mag[512];
            sincosf(phase[512], &s5, &c5);
        }
        // S8 preload: one d2w row
        float4 wF = *(const float4*)(d2w + (size_t)ew*HID + lane*4);
        float bF = d2b[ew];

        waitf(CNT(1), 16, tid);
        {
            float4 x = __ldcg((const float4*)&g_h2[lane*4]);
            float a0 = wD0.x*x.x+wD0.y*x.y+wD0.z*x.z+wD0.w*x.w;
            float a1 = wD1.x*x.x+wD1.y*x.y+wD1.z*x.z+wD1.w*x.w;
            wsum2(a0, a1);
            if (lane == 0){
                float e0 = sigm(a0+b0)*m0, e1 = sigm(a1+b1)*m1;
                g_sr[r0]   = e0*c0;  g_si[r0]   = e0*s0;
                g_sr[r0+1] = e1*c1;  g_si[r0+1] = e1*s1;
            }
            if (ew == 0){
                float a5 = w512.x*x.x+w512.y*x.y+w512.z*x.z+w512.w*x.w;
                a5 = wsum(a5);
                if (lane == 0){
                    float e5 = sigm(a5+b5)*m5;
                    g_sr[512] = e5*c5;  g_si[512] = e5*s5;
                }
            }
        }
        signalf(CNT(2), tid);

        waitf(CNT(6), 16, tid);
        {
            float4 x = __ldcg((const float4*)&g_h2b[lane*4]);
            float a = wF.x*x.x+wF.y*x.y+wF.z*x.z+wF.w*x.w;
            a = wsum(a);
            if (lane == 0){
                float encv = __ldcg(&g_enc[ew]);
                g_est[ew] = sigm(a+bF) * encv;
            }
        }
        signalf(CNT(7), tid);
    }
    else {
        // ================= F: iDFT (S4) then encoder (S5) =================
        int fw = (cta-96)*8 + wid;         // 0..255
        // twiddle table per CTA
        for (int m = tid; m < WIN; m += NTHR){
            float s, c; sincospif((float)m * (1.0f/512.0f), &s, &c);
            s_tw[m + (m >> 5)] = make_float2(c, s);
        }
        // S5 preload: encoder row fw (32 floats/lane)
        float4 wE[8];
        {
            const float* wr = encw + (size_t)fw*WIN;
#pragma unroll
            for (int c = 0; c < 8; c++) wE[c] = *(const float4*)(wr + c*128 + lane*4);
        }

        waitf(CNT(2), 32, tid);
        {
            float dc  = __ldcg(&g_sr[0]);
            float nyq = __ldcg(&g_sr[512]);
            float srv[16], siv[16];
#pragma unroll
            for (int t = 0; t < 16; t++){
                int k = 1 + lane + 32*t;
                srv[t] = (k < 512) ? __ldcg(&g_sr[k]) : 0.f;
                siv[t] = (k < 512) ? __ldcg(&g_si[k]) : 0.f;
            }
            int n0 = fw*4;
            float a0=0.f,a1=0.f,a2=0.f,a3=0.f;
#pragma unroll
            for (int t = 0; t < 16; t++){
                int k = 1 + lane + 32*t;
                float sr_ = srv[t], si_ = siv[t];
                int base = (k * n0) & (WIN-1);
                int i0 = base,            j0 = i0 + (i0>>5);
                int i1 = (base+k)&(WIN-1),   j1 = i1 + (i1>>5);
                int i2 = (base+2*k)&(WIN-1), j2 = i2 + (i2>>5);
                int i3 = (base+3*k)&(WIN-1), j3 = i3 + (i3>>5);
                float2 q0 = s_tw[j0], q1 = s_tw[j1], q2 = s_tw[j2], q3 = s_tw[j3];
                a0 = fmaf(sr_, q0.x, a0); a0 = fmaf(-si_, q0.y, a0);
                a1 = fmaf(sr_, q1.x, a1); a1 = fmaf(-si_, q1.y, a1);
                a2 = fmaf(sr_, q2.x, a2); a2 = fmaf(-si_, q2.y, a2);
                a3 = fmaf(sr_, q3.x, a3); a3 = fmaf(-si_, q3.y, a3);
            }
            wsum4(a0,a1,a2,a3);
            if (lane == 0){
                g_y1[n0+0] = (dc + nyq + 2.0f*a0) * (1.0f/1024.0f);
                g_y1[n0+1] = (dc - nyq + 2.0f*a1) * (1.0f/1024.0f);
                g_y1[n0+2] = (dc + nyq + 2.0f*a2) * (1.0f/1024.0f);
                g_y1[n0+3] = (dc - nyq + 2.0f*a3) * (1.0f/1024.0f);
            }
        }
        signalf(CNT(3), tid);

        waitf(CNT(3), 32, tid);
        {
            float acc = 0.f;
#pragma unroll
            for (int c = 0; c < 8; c++){
                float4 y = __ldcg((const float4*)&g_y1[c*128 + lane*4]);
                acc = fmaf(wE[c].x, y.x, acc); acc = fmaf(wE[c].y, y.y, acc);
                acc = fmaf(wE[c].z, y.z, acc); acc = fmaf(wE[c].w, y.w, acc);
            }
            acc = wsum(acc);
            if (lane == 0) g_enc[fw] = acc;
        }
        signalf(CNT(4), tid);
    }

    // ================= S9: decoder (all 1024 warps, row gw) =================
    waitf(CNT(7), 32, tid);
    {
        float4 e0 = __ldcg((const float4*)&g_est[lane*8]);
        float4 e1 = __ldcg((const float4*)&g_est[lane*8 + 4]);
        float acc = dec0.x*e0.x + dec0.y*e0.y + dec0.z*e0.z + dec0.w*e0.w
                  + dec1.x*e1.x + dec1.y*e1.y + dec1.z*e1.z + dec1.w*e1.w;
        acc = wsum(acc);
        if (lane == 0) out[gw] = acc;
    }

    // ================= done-count + counter reset =================
    __syncthreads();
    if (tid == 0) redrel(CNT(8));
    if (cta == 0 && tid == 0){
        while (ldacq(CNT(8)) < NBLK) {}
#pragma unroll
        for (int i = 0; i < 9; i++) *((volatile unsigned*)CNT(i)) = 0u;
    }
}

extern "C" void kernel_launch(void* const* d_in, const int* in_sizes, int n_in,
                              void* d_out, int out_size)
{
    (void)in_sizes; (void)n_in; (void)out_size;
    dtln_kernel<<<NBLK, NTHR>>>(
        (const float*)d_in[0],  (const float*)d_in[1],
        (const float*)d_in[2],  (const float*)d_in[3],
        (const float*)d_in[4],  (const float*)d_in[5],
        (const float*)d_in[6],  (const float*)d_in[7],
        (const float*)d_in[8],  (const float*)d_in[9],
        (const float*)d_in[10], (const float*)d_in[11],
        (const float*)d_in[12], (const float*)d_in[13],
        (const float*)d_in[14], (const float*)d_in[15],
        (const float*)d_in[16],
        (const float*)d_in[17], (const float*)d_in[18],
        (const float*)d_in[19], (const float*)d_in[20],
        (const float*)d_in[21], (const float*)d_in[22],
        (const float*)d_in[23], (const float*)d_in[24],
        (const float*)d_in[25], (const float*)d_in[26],
        (const float*)d_in[27],
        (float*)d_out);
}

// round 10
// speedup vs baseline: 1.6521x; 1.1358x over previous
#include <cuda_runtime.h>
#include <math.h>

#define NBLK 128
#define NTHR 256
#define HID  128
#define BINS 513
#define WIN  1024
#define ENCN 256

// ---------------- device scratch ----------------
__device__ __align__(16) float g_h1[HID], g_h2[HID], g_h1b[HID], g_h2b[HID];
__device__ __align__(16) float g_sr[BINS+3], g_si[BINS+3];
__device__ __align__(16) float g_encP[32*ENCN];     // partial enc rows (overwritten each launch)
__device__ __align__(16) float g_enc[ENCN];
__device__ unsigned g_cnt[7*32];                    // counters, 128B apart
#define CNT(i) (&g_cnt[(i)*32])
// counters: 0:h1(16) 1:h2(16) 2:spec(32) 3:encP(32) 4:h1b(16) 5:h2b(16) 6:done(128)

// ---------------- dynamic smem layout (bytes) ----------------
#define OFF_D2W   0                   // 256 rows × 132 floats (pad 4) = 135168
#define OFF_ENCWT 135168              // 32 × 257 floats = 32896
#define OFF_Y1S   168064              // 32 floats
#define OFF_EST   168192              // 256 floats
#define OFF_H2B   169216              // 128 floats
#define OFF_RED   169728              // 8 floats
#define OFF_RED2  169760              // 8 floats
#define OFF_ENCN  169792              // 256 floats
#define SMEM_TOTAL 170816

__device__ __forceinline__ float sigm(float x){ return 1.0f/(1.0f+__expf(-x)); }

__device__ __forceinline__ float wsum(float v){
#pragma unroll
    for (int o = 16; o > 0; o >>= 1) v += __shfl_xor_sync(0xffffffffu, v, o);
    return v;
}
__device__ __forceinline__ void wsum2(float& a, float& b){
#pragma unroll
    for (int o = 16; o > 0; o >>= 1){
        a += __shfl_xor_sync(0xffffffffu, a, o);
        b += __shfl_xor_sync(0xffffffffu, b, o);
    }
}
__device__ __forceinline__ void wsum4(float& a, float& b, float& c, float& d){
#pragma unroll
    for (int o = 16; o > 0; o >>= 1){
        a += __shfl_xor_sync(0xffffffffu, a, o);
        b += __shfl_xor_sync(0xffffffffu, b, o);
        c += __shfl_xor_sync(0xffffffffu, c, o);
        d += __shfl_xor_sync(0xffffffffu, d, o);
    }
}

__device__ __forceinline__ void redrel(unsigned* p){
    asm volatile("red.release.gpu.global.add.u32 [%0], 1;" :: "l"(p) : "memory");
}
__device__ __forceinline__ unsigned ldacq(const unsigned* p){
    unsigned v;
    asm volatile("ld.acquire.gpu.global.u32 %0, [%1];" : "=r"(v) : "l"(p) : "memory");
    return v;
}
__device__ __forceinline__ void signalf(unsigned* c, int tid){
    __syncthreads();
    if (tid == 0){
        asm volatile("fence.acq_rel.gpu;" ::: "memory");
        redrel(c);
    }
}
__device__ __forceinline__ void waitf(unsigned* c, unsigned tgt, int tid){
    if (tid == 0){ while (ldacq(c) < tgt) {} }
    __syncthreads();
}

__global__ void __launch_bounds__(NTHR, 1) dtln_kernel(
    const float* __restrict__ mag,   const float* __restrict__ phase,
    const float* __restrict__ st1,   const float* __restrict__ st2,
    const float* __restrict__ wih10, const float* __restrict__ whh10,
    const float* __restrict__ bih10, const float* __restrict__ bhh10,
    const float* __restrict__ wih11, const float* __restrict__ whh11,
    const float* __restrict__ bih11, const float* __restrict__ bhh11,
    const float* __restrict__ d1w,   const float* __restrict__ d1b,
    const float* __restrict__ encw,  const float* __restrict__ gamma_,
    const float* __restrict__ beta_,
    const float* __restrict__ wih20, const float* __restrict__ whh20,
    const float* __restrict__ bih20, const float* __restrict__ bhh20,
    const float* __restrict__ wih21, const float* __restrict__ whh21,
    const float* __restrict__ bih21, const float* __restrict__ bhh21,
    const float* __restrict__ d2w,   const float* __restrict__ d2b,
    const float* __restrict__ decw,
    float* __restrict__ out)
{
    extern __shared__ char dsm[];
    const int tid  = threadIdx.x;
    const int lane = tid & 31;
    const int wid  = tid >> 5;
    const int cta  = blockIdx.x;
    const int gw   = cta * 8 + wid;        // 0..1023

    float4* d2wP   = (float4*)(dsm + OFF_D2W);     // [e*33 + k4]
    float*  estS   = (float*)(dsm + OFF_EST);
    float*  h2bS   = (float*)(dsm + OFF_H2B);

    // d2w smem fill: float4 i -> e=i>>5, k4=i&31 ; store at e*33+k4 (pad kills conflicts)
    #define FILL_D2W() do{ \
        const float4* s4 = (const float4*)d2w; \
        for (int i = tid; i < 256*32; i += NTHR){ int e = i >> 5, k4 = i & 31; d2wP[e*33 + k4] = s4[i]; } \
    }while(0)

    float4 dec0, dec1; float d2bv, encv = 0.f;
    #define LOAD_DEC() do{ \
        const float* wr = decw + (size_t)gw*ENCN; \
        dec0 = *(const float4*)(wr + lane*8); \
        dec1 = *(const float4*)(wr + lane*8 + 4); \
        d2bv = d2b[tid]; \
    }while(0)

    if (cta < 16){
        // ================= A: LSTM1 layer0 (S1) =================
        int j = gw;
        float wiA[4][17], whA[4][4], bA[4], xrA[17], hrA[4];
#pragma unroll
        for (int g = 0; g < 4; g++){
            const float* w = wih10 + (size_t)(g*HID + j)*BINS;
#pragma unroll
            for (int i = 0; i < 17; i++){ int k = lane + 32*i; wiA[g][i] = (k < BINS) ? w[k] : 0.f; }
            const float* wh = whh10 + (size_t)(g*HID + j)*HID;
#pragma unroll
            for (int i = 0; i < 4; i++) whA[g][i] = wh[lane + 32*i];
            bA[g] = bih10[g*HID + j] + bhh10[g*HID + j];
        }
#pragma unroll
        for (int i = 0; i < 17; i++){ int k = lane + 32*i; xrA[i] = (k < BINS) ? mag[k] : 0.f; }
#pragma unroll
        for (int i = 0; i < 4; i++) hrA[i] = st1[lane + 32*i];
        float cprev = st1[2*HID + j];

        float a0=0.f,a1=0.f,a2=0.f,a3=0.f;
#pragma unroll
        for (int i = 0; i < 17; i++){
            float x = xrA[i];
            a0 = fmaf(wiA[0][i], x, a0); a1 = fmaf(wiA[1][i], x, a1);
            a2 = fmaf(wiA[2][i], x, a2); a3 = fmaf(wiA[3][i], x, a3);
        }
#pragma unroll
        for (int i = 0; i < 4; i++){
            float h = hrA[i];
            a0 = fmaf(whA[0][i], h, a0); a1 = fmaf(whA[1][i], h, a1);
            a2 = fmaf(whA[2][i], h, a2); a3 = fmaf(whA[3][i], h, a3);
        }
        wsum4(a0,a1,a2,a3);
        if (lane == 0){
            float c2 = sigm(a1+bA[1])*cprev + sigm(a0+bA[0])*tanhf(a2+bA[2]);
            float h2 = sigm(a3+bA[3])*tanhf(c2);
            out[WIN + j] = h2; out[WIN + 2*HID + j] = c2;
            g_h1[j] = h2;
        }
        signalf(CNT(0), tid);
        FILL_D2W(); LOAD_DEC();
    }
    else if (cta < 32){
        // ================= B: LSTM1 layer1 (S2) =================
        int j = gw - 128;
        float4 wi[4], wh[4]; float b[4];
#pragma unroll
        for (int g = 0; g < 4; g++){
            wi[g] = *(const float4*)(wih11 + (size_t)(g*HID + j)*HID + lane*4);
            wh[g] = *(const float4*)(whh11 + (size_t)(g*HID + j)*HID + lane*4);
            b[g]  = bih11[g*HID + j] + bhh11[g*HID + j];
        }
        float4 hr = *(const float4*)(st1 + HID + lane*4);
        float cprev = st1[3*HID + j];
        FILL_D2W(); LOAD_DEC();
        waitf(CNT(0), 16, tid);
        float4 x = __ldcg((const float4*)&g_h1[lane*4]);
        float a0 = wi[0].x*x.x+wi[0].y*x.y+wi[0].z*x.z+wi[0].w*x.w + wh[0].x*hr.x+wh[0].y*hr.y+wh[0].z*hr.z+wh[0].w*hr.w;
        float a1 = wi[1].x*x.x+wi[1].y*x.y+wi[1].z*x.z+wi[1].w*x.w + wh[1].x*hr.x+wh[1].y*hr.y+wh[1].z*hr.z+wh[1].w*hr.w;
        float a2 = wi[2].x*x.x+wi[2].y*x.y+wi[2].z*x.z+wi[2].w*x.w + wh[2].x*hr.x+wh[2].y*hr.y+wh[2].z*hr.z+wh[2].w*hr.w;
        float a3 = wi[3].x*x.x+wi[3].y*x.y+wi[3].z*x.z+wi[3].w*x.w + wh[3].x*hr.x+wh[3].y*hr.y+wh[3].z*hr.z+wh[3].w*hr.w;
        wsum4(a0,a1,a2,a3);
        if (lane == 0){
            float c2 = sigm(a1+b[1])*cprev + sigm(a0+b[0])*tanhf(a2+b[2]);
            float h2 = sigm(a3+b[3])*tanhf(c2);
            out[WIN + HID + j] = h2; out[WIN + 3*HID + j] = c2;
            g_h2[j] = h2;
        }
        signalf(CNT(1), tid);
    }
    else if (cta < 48){
        // ================= C: sum partials + norm + LSTM2 layer0 =================
        int j = (cta-32)*8 + wid;
        float4 wi0[4], wi1[4], wh[4]; float b[4];
#pragma unroll
        for (int g = 0; g < 4; g++){
            wi0[g] = *(const float4*)(wih20 + (size_t)(g*HID + j)*ENCN + lane*8);
            wi1[g] = *(const float4*)(wih20 + (size_t)(g*HID + j)*ENCN + lane*8 + 4);
            wh[g]  = *(const float4*)(whh20 + (size_t)(g*HID + j)*HID + lane*4);
            b[g]   = bih20[g*HID + j] + bhh20[g*HID + j];
        }
        float4 hr = *(const float4*)(st2 + lane*4);
        float cprev = st2[2*HID + j];
        float gamv = gamma_[tid], betv = beta_[tid];
        FILL_D2W(); LOAD_DEC();

        waitf(CNT(3), 32, tid);
        float v = 0.f;
#pragma unroll
        for (int s = 0; s < 32; s++) v += __ldcg(&g_encP[s*ENCN + tid]);
        if (cta == 32) *((float*)&g_enc[tid]) = v;     // plain STG; covered by C4 fence

        // norm (single syncthreads)
        float sv = v, sq = v*v;
        wsum2(sv, sq);
        float* red  = (float*)(dsm + OFF_RED);
        float* red2 = (float*)(dsm + OFF_RED2);
        if (lane == 0){ red[wid] = sv; red2[wid] = sq; }
        __syncthreads();
        float tot = 0.f, tot2 = 0.f;
#pragma unroll
        for (int i = 0; i < 8; i++){ tot += red[i]; tot2 += red2[i]; }
        float mean = tot * (1.0f/ENCN);
        float var  = tot2 * (1.0f/ENCN) - mean*mean;
        float rstd = rsqrtf(var + 1e-7f);
        float* encn = (float*)(dsm + OFF_ENCN);
        encn[tid] = (v - mean) * rstd * gamv + betv;
        __syncthreads();

        float4 x0 = *(const float4*)&encn[lane*8];
        float4 x1 = *(const float4*)&encn[lane*8 + 4];
        float a0 = wi0[0].x*x0.x+wi0[0].y*x0.y+wi0[0].z*x0.z+wi0[0].w*x0.w + wi1[0].x*x1.x+wi1[0].y*x1.y+wi1[0].z*x1.z+wi1[0].w*x1.w
                 + wh[0].x*hr.x+wh[0].y*hr.y+wh[0].z*hr.z+wh[0].w*hr.w;
        float a1 = wi0[1].x*x0.x+wi0[1].y*x0.y+wi0[1].z*x0.z+wi0[1].w*x0.w + wi1[1].x*x1.x+wi1[1].y*x1.y+wi1[1].z*x1.z+wi1[1].w*x1.w
                 + wh[1].x*hr.x+wh[1].y*hr.y+wh[1].z*hr.z+wh[1].w*hr.w;
        float a2 = wi0[2].x*x0.x+wi0[2].y*x0.y+wi0[2].z*x0.z+wi0[2].w*x0.w + wi1[2].x*x1.x+wi1[2].y*x1.y+wi1[2].z*x1.z+wi1[2].w*x1.w
                 + wh[2].x*hr.x+wh[2].y*hr.y+wh[2].z*hr.z+wh[2].w*hr.w;
        float a3 = wi0[3].x*x0.x+wi0[3].y*x0.y+wi0[3].z*x0.z+wi0[3].w*x0.w + wi1[3].x*x1.x+wi1[3].y*x1.y+wi1[3].z*x1.z+wi1[3].w*x1.w
                 + wh[3].x*hr.x+wh[3].y*hr.y+wh[3].z*hr.z+wh[3].w*hr.w;
        wsum4(a0,a1,a2,a3);
        if (lane == 0){
            float c2 = sigm(a1+b[1])*cprev + sigm(a0+b[0])*tanhf(a2+b[2]);
            float h2 = sigm(a3+b[3])*tanhf(c2);
            out[WIN + 4*HID + j] = h2; out[WIN + 6*HID + j] = c2;
            g_h1b[j] = h2;
        }
        signalf(CNT(4), tid);
    }
    else if (cta < 64){
        // ================= D: LSTM2 layer1 =================
        int j = (cta-48)*8 + wid;
        float4 wi[4], wh[4]; float b[4];
#pragma unroll
        for (int g = 0; g < 4; g++){
            wi[g] = *(const float4*)(wih21 + (size_t)(g*HID + j)*HID + lane*4);
            wh[g] = *(const float4*)(whh21 + (size_t)(g*HID + j)*HID + lane*4);
            b[g]  = bih21[g*HID + j] + bhh21[g*HID + j];
        }
        float4 hr = *(const float4*)(st2 + HID + lane*4);
        float cprev = st2[3*HID + j];
        FILL_D2W(); LOAD_DEC();
        waitf(CNT(4), 16, tid);
        float4 x = __ldcg((const float4*)&g_h1b[lane*4]);
        float a0 = wi[0].x*x.x+wi[0].y*x.y+wi[0].z*x.z+wi[0].w*x.w + wh[0].x*hr.x+wh[0].y*hr.y+wh[0].z*hr.z+wh[0].w*hr.w;
        float a1 = wi[1].x*x.x+wi[1].y*x.y+wi[1].z*x.z+wi[1].w*x.w + wh[1].x*hr.x+wh[1].y*hr.y+wh[1].z*hr.z+wh[1].w*hr.w;
        float a2 = wi[2].x*x.x+wi[2].y*x.y+wi[2].z*x.z+wi[2].w*x.w + wh[2].x*hr.x+wh[2].y*hr.y+wh[2].z*hr.z+wh[2].w*hr.w;
        float a3 = wi[3].x*x.x+wi[3].y*x.y+wi[3].z*x.z+wi[3].w*x.w + wh[3].x*hr.x+wh[3].y*hr.y+wh[3].z*hr.z+wh[3].w*hr.w;
        wsum4(a0,a1,a2,a3);
        if (lane == 0){
            float c2 = sigm(a1+b[1])*cprev + sigm(a0+b[0])*tanhf(a2+b[2]);
            float h2 = sigm(a3+b[3])*tanhf(c2);
            out[WIN + 5*HID + j] = h2; out[WIN + 7*HID + j] = c2;
            g_h2b[j] = h2;
        }
        signalf(CNT(5), tid);
    }
    else if (cta < 96){
        // ================= E: dense1 -> spectrum =================
        int ew = (cta-64)*8 + wid;         // 0..255
        int r0 = 2*ew;
        float4 wD0 = *(const float4*)(d1w + (size_t)(r0+0)*HID + lane*4);
        float4 wD1 = *(const float4*)(d1w + (size_t)(r0+1)*HID + lane*4);
        float b0 = d1b[r0+0], b1 = d1b[r0+1];
        float m0 = mag[r0+0], m1 = mag[r0+1];
        float c0,s0,c1,s1;
        sincosf(phase[r0+0], &s0, &c0);  sincosf(phase[r0+1], &s1, &c1);
        float4 w512 = make_float4(0.f,0.f,0.f,0.f);
        float b5=0.f, m5=0.f, c5=1.f, s5=0.f;
        if (ew == 0){
            w512 = *(const float4*)(d1w + (size_t)512*HID + lane*4);
            b5 = d1b[512]; m5 = mag[512];
            sincosf(phase[512], &s5, &c5);
        }
        FILL_D2W(); LOAD_DEC();

        waitf(CNT(1), 16, tid);
        float4 x = __ldcg((const float4*)&g_h2[lane*4]);
        float a0 = wD0.x*x.x+wD0.y*x.y+wD0.z*x.z+wD0.w*x.w;
        float a1 = wD1.x*x.x+wD1.y*x.y+wD1.z*x.z+wD1.w*x.w;
        wsum2(a0, a1);
        if (lane == 0){
            float e0 = sigm(a0+b0)*m0, e1 = sigm(a1+b1)*m1;
            g_sr[r0]   = e0*c0;  g_si[r0]   = e0*s0;
            g_sr[r0+1] = e1*c1;  g_si[r0+1] = e1*s1;
        }
        if (ew == 0){
            float a5 = w512.x*x.x+w512.y*x.y+w512.z*x.z+w512.w*x.w;
            a5 = wsum(a5);
            if (lane == 0){
                float e5 = sigm(a5+b5)*m5;
                g_sr[512] = e5*c5;  g_si[512] = e5*s5;
            }
        }
        signalf(CNT(2), tid);
    }
    else {
        // ================= F: iDFT (recurrence) + partial encoder =================
        int fw = (cta-96)*8 + wid;         // 0..255
        int n_base = (cta-96)*32;
        float* encwT = (float*)(dsm + OFF_ENCWT);   // [nl*257 + e]
        float* y1s   = (float*)(dsm + OFF_Y1S);
        for (int i = tid; i < 256*32; i += NTHR){
            int e = i >> 5, nl = i & 31;
            encwT[nl*257 + e] = encw[(size_t)e*WIN + n_base + nl];
        }
        FILL_D2W(); LOAD_DEC();

        waitf(CNT(2), 32, tid);
        {
            float dc  = __ldcg(&g_sr[0]);
            float nyq = __ldcg(&g_sr[512]);
            float srv[16], siv[16];
#pragma unroll
            for (int t = 0; t < 16; t++){
                int k = 1 + lane + 32*t;
                srv[t] = (k < 512) ? __ldcg(&g_sr[k]) : 0.f;
                siv[t] = (k < 512) ? __ldcg(&g_si[k]) : 0.f;
            }
            int n0 = fw*4;
            float cc[4], ss[4], cd[4], sd[4], acc[4];
#pragma unroll
            for (int q = 0; q < 4; q++){
                int n = n0 + q;
                int m0i = ((1+lane)*n) & (WIN-1);
                int mdi = (32*n) & (WIN-1);
                float sA, cA, sD, cD;
                sincospif((float)m0i * (1.0f/512.0f), &sA, &cA);
                sincospif((float)mdi * (1.0f/512.0f), &sD, &cD);
                cc[q] = cA; ss[q] = sA; cd[q] = cD; sd[q] = sD;
                acc[q] = 0.f;
            }
#pragma unroll
            for (int t = 0; t < 16; t++){
                float sr_ = srv[t], si_ = siv[t];
#pragma unroll
                for (int q = 0; q < 4; q++){
                    acc[q] = fmaf(sr_, cc[q], acc[q]);
                    acc[q] = fmaf(-si_, ss[q], acc[q]);
                    float cn = cc[q]*cd[q] - ss[q]*sd[q];
                    ss[q]    = ss[q]*cd[q] + cc[q]*sd[q];
                    cc[q]    = cn;
                }
            }
            wsum4(acc[0],acc[1],acc[2],acc[3]);
            if (lane == 0){
#pragma unroll
                for (int q = 0; q < 4; q++){
                    int n = n0 + q;
                    float ny = (n & 1) ? -nyq : nyq;
                    y1s[wid*4 + q] = (dc + 2.0f*acc[q] + ny) * (1.0f/1024.0f);
                }
            }
        }
        __syncthreads();
        {
            float acc = 0.f;
#pragma unroll
            for (int nl = 0; nl < 32; nl++)
                acc = fmaf(encwT[nl*257 + tid], y1s[nl], acc);
            g_encP[(cta-96)*ENCN + tid] = acc;
        }
        signalf(CNT(3), tid);
    }

    // ================= final: est (local) + decoder =================
    waitf(CNT(5), 16, tid);
    if (tid < HID) h2bS[tid] = __ldcg(&g_h2b[tid]);
    encv = __ldcg(&g_enc[tid]);
    __syncthreads();
    {
        const float4* h2b4 = (const float4*)h2bS;
        float acc = 0.f;
#pragma unroll
        for (int k4 = 0; k4 < 32; k4++){
            float4 w = d2wP[tid*33 + k4];
            float4 h = h2b4[k4];
            acc += w.x*h.x + w.y*h.y + w.z*h.z + w.w*h.w;
        }
        estS[tid] = sigm(acc + d2bv) * encv;
    }
    __syncthreads();
    {
        const float4* est4 = (const float4*)estS;
        float4 e0 = est4[lane*2], e1 = est4[lane*2 + 1];
        float acc = dec0.x*e0.x + dec0.y*e0.y + dec0.z*e0.z + dec0.w*e0.w
                  + dec1.x*e1.x + dec1.y*e1.y + dec1.z*e1.z + dec1.w*e1.w;
        acc = wsum(acc);
        if (lane == 0) out[gw] = acc;
    }

    // ================= done-count + counter reset =================
    __syncthreads();
    if (tid == 0) redrel(CNT(6));
    if (cta == 0 && tid == 0){
        while (ldacq(CNT(6)) < NBLK) {}
#pragma unroll
        for (int i = 0; i < 7; i++) *((volatile unsigned*)CNT(i)) = 0u;
    }
}

extern "C" void kernel_launch(void* const* d_in, const int* in_sizes, int n_in,
                              void* d_out, int out_size)
{
    (void)in_sizes; (void)n_in; (void)out_size;
    static int configured = 0;
    if (!configured){
        cudaFuncSetAttribute(dtln_kernel, cudaFuncAttributeMaxDynamicSharedMemorySize, SMEM_TOTAL);
        configured = 1;
    }
    dtln_kernel<<<NBLK, NTHR, SMEM_TOTAL>>>(
        (const float*)d_in[0],  (const float*)d_in[1],
        (const float*)d_in[2],  (const float*)d_in[3],
        (const float*)d_in[4],  (const float*)d_in[5],
        (const float*)d_in[6],  (const float*)d_in[7],
        (const float*)d_in[8],  (const float*)d_in[9],
        (const float*)d_in[10], (const float*)d_in[11],
        (const float*)d_in[12], (const float*)d_in[13],
        (const float*)d_in[14], (const float*)d_in[15],
        (const float*)d_in[16],
        (const float*)d_in[17], (const float*)d_in[18],
        (const float*)d_in[19], (const float*)d_in[20],
        (const float*)d_in[21], (const float*)d_in[22],
        (const float*)d_in[23], (const float*)d_in[24],
        (const float*)d_in[25], (const float*)d_in[26],
        (const float*)d_in[27],
        (float*)d_out);
}